// round 15
// baseline (speedup 1.0000x reference)
#include <cuda_runtime.h>
#include <cuda_fp16.h>
#include <math.h>
#include <float.h>
#include <stdint.h>

#define SQ   2048
#define HID  4096
#define NH   32
#define NKV  8
#define HD   128
#define KVD  1024   // NKV * HD
#define QKVD 6144   // HID + 2*KVD

// Scratch (allocation-free rule: __device__ globals)
__device__ float  g_QKV[SQ * QKVD];      // 48 MB  fused QKV proj out fp32
__device__ __half g_Qh[SQ * HID];        // 16 MB  post-RoPE, scaled, fp16
__device__ __half g_Kh[SQ * KVD];        // 4 MB   post-RoPE fp16
__device__ __half g_Vth[KVD * SQ];       // 4 MB   V^T [kv*HD+d][s] fp16
__device__ __half g_Ah[SQ * HID];        // 16 MB  attention out fp16
__device__ __half g_Xh[SQ * HID];        // 16 MB
__device__ __half g_Wqkvh[QKVD * HID];   // 48 MB  [Wq; Wk; Wv] rows
__device__ __half g_Woh[HID * HID];      // 32 MB

__device__ __forceinline__ uint32_t smem_u32(const void* p) {
    uint32_t a;
    asm("{ .reg .u64 t; cvta.to.shared.u64 t, %1; cvt.u32.u64 %0, t; }" : "=r"(a) : "l"(p));
    return a;
}
__device__ __forceinline__ void cp_async16(uint32_t dst, const void* src) {
    asm volatile("cp.async.cg.shared.global [%0], [%1], 16;" :: "r"(dst), "l"(src) : "memory");
}
#define CP_COMMIT() asm volatile("cp.async.commit_group;" ::: "memory")

__device__ __forceinline__ void mma_h(float* c, const uint32_t* a, const uint32_t* b) {
    asm volatile(
        "mma.sync.aligned.m16n8k16.row.col.f32.f16.f16.f32 "
        "{%0,%1,%2,%3}, {%4,%5,%6,%7}, {%8,%9}, {%0,%1,%2,%3};"
        : "+f"(c[0]), "+f"(c[1]), "+f"(c[2]), "+f"(c[3])
        : "r"(a[0]), "r"(a[1]), "r"(a[2]), "r"(a[3]), "r"(b[0]), "r"(b[1]));
}
__device__ __forceinline__ void ldsm4(uint32_t& r0, uint32_t& r1, uint32_t& r2,
                                      uint32_t& r3, uint32_t addr) {
    asm volatile("ldmatrix.sync.aligned.m8n8.x4.shared.b16 {%0,%1,%2,%3}, [%4];"
                 : "=r"(r0), "=r"(r1), "=r"(r2), "=r"(r3) : "r"(addr));
}

// ---------------------------------------------------------------------------
// fp32 -> fp16 (RN) conversion
// ---------------------------------------------------------------------------
__global__ void f2h_kernel(const float4* __restrict__ in,
                           uint2* __restrict__ out, int n4) {
    int i = blockIdx.x * blockDim.x + threadIdx.x;
    if (i < n4) {
        float4 v = in[i];
        __half2 lo = __floats2half2_rn(v.x, v.y);
        __half2 hi = __floats2half2_rn(v.z, v.w);
        out[i] = make_uint2(*(uint32_t*)&lo, *(uint32_t*)&hi);
    }
}

// ---------------------------------------------------------------------------
// fp16 GEMM (R13 structure, K-stage 64): C[M,N] = A[M,K] @ B[N,K]^T.
// CTA 128x128, 8 warps (2x4), warp tile 64x32, K staged 64 halves,
// double-buffered cp.async. Row stride 72 halves (144 B): ldmatrix phase
// rows start at words 36r mod 32 = {0,4,...,28} -> conflict-free.
// Smem: 2 stages x (A 18432 + B 18432) = 73728 B -> 2 CTAs/SM.
// ---------------------------------------------------------------------------
#define GH_STAGE_B   18432          // one tile (128*72 halves)
#define GH_B_OFF     36864          // B region offset (2 A stages first)
#define GH_SMEM      73728

__global__ __launch_bounds__(256) void gemm_h(const __half* __restrict__ A,
                                              const __half* __restrict__ B,
                                              float* __restrict__ C,
                                              int M, int N, int K) {
    extern __shared__ char smc[];
    uint32_t sbase = smem_u32(smc);
    int tid = threadIdx.x, lane = tid & 31, wid = tid >> 5;
    int wm = (wid >> 2) * 64;
    int wn = (wid & 3) * 32;
    int g = lane >> 2, t = lane & 3;
    int lrow = tid >> 1;
    uint32_t lcolB = (uint32_t)(tid & 1) * 64;   // byte offset within row (32 halves)
    // staging write bases (stage 0)
    uint32_t sA0 = sbase + (uint32_t)lrow * 144 + lcolB;
    uint32_t sB0 = sA0 + GH_B_OFF;
    // ldmatrix read bases (stage 0): rows (lane&15), k-offset 8*(lane>>4)
    int l16 = lane & 15, lk8 = (lane >> 4) * 8;
    uint32_t aB0 = sbase + (uint32_t)(wm + l16) * 144 + (uint32_t)lk8 * 2;
    uint32_t bB0 = sbase + GH_B_OFF + (uint32_t)(wn + l16) * 144 + (uint32_t)lk8 * 2;

    float acc[4][4][4] = {};

    int m0 = blockIdx.y * 128, n0 = blockIdx.x * 128;
    const __half* Ag = A + (size_t)(m0 + lrow) * K + (tid & 1) * 32;
    const __half* Bg = B + (size_t)(n0 + lrow) * K + (tid & 1) * 32;
    int S = K >> 6;   // stages of 64 halves

#define GH_LOAD(st) do { \
        uint32_t _o = (uint32_t)((st) & 1) * GH_STAGE_B; \
        const __half* _a  = Ag + (st) * 64; \
        const __half* _bg = Bg + (st) * 64; \
        cp_async16(sA0 + _o,      _a);       cp_async16(sA0 + _o + 16, _a + 8); \
        cp_async16(sA0 + _o + 32, _a + 16);  cp_async16(sA0 + _o + 48, _a + 24); \
        cp_async16(sB0 + _o,      _bg);      cp_async16(sB0 + _o + 16, _bg + 8); \
        cp_async16(sB0 + _o + 32, _bg + 16); cp_async16(sB0 + _o + 48, _bg + 24); \
        CP_COMMIT(); \
    } while (0)

    GH_LOAD(0);
    GH_LOAD(1);

    for (int kt = 0; kt < S; kt++) {
        if (kt < S - 1) asm volatile("cp.async.wait_group 1;" ::: "memory");
        else            asm volatile("cp.async.wait_group 0;" ::: "memory");
        __syncthreads();
        uint32_t off = (uint32_t)(kt & 1) * GH_STAGE_B;
        uint32_t aB = aB0 + off, bB = bB0 + off;
#pragma unroll
        for (int kk = 0; kk < 4; kk++) {        // four k16 steps; byte off kk*32
            uint32_t a[4][4], b[4][2];
#pragma unroll
            for (int i = 0; i < 4; i++)
                ldsm4(a[i][0], a[i][1], a[i][2], a[i][3],
                      aB + (uint32_t)(i * 16 * 144 + kk * 32));
#pragma unroll
            for (int p = 0; p < 2; p++)
                ldsm4(b[2 * p][0], b[2 * p + 1][0], b[2 * p][1], b[2 * p + 1][1],
                      bB + (uint32_t)(p * 16 * 144 + kk * 32));
#pragma unroll
            for (int i = 0; i < 4; i++)
#pragma unroll
                for (int j = 0; j < 4; j++)
                    mma_h(acc[i][j], a[i], b[j]);
        }
        __syncthreads();
        if (kt + 2 < S) GH_LOAD(kt + 2);
    }
#undef GH_LOAD

#pragma unroll
    for (int i = 0; i < 4; i++) {
#pragma unroll
        for (int j = 0; j < 4; j++) {
            int r0 = m0 + wm + i * 16 + g;
            int cc = n0 + wn + j * 8 + t * 2;
            *(float2*)(C + (size_t)r0 * N + cc)       = make_float2(acc[i][j][0], acc[i][j][1]);
            *(float2*)(C + (size_t)(r0 + 8) * N + cc) = make_float2(acc[i][j][2], acc[i][j][3]);
        }
    }
}

// ---------------------------------------------------------------------------
// Fused flash attention (fp16 mma) — unchanged (proven).
// ---------------------------------------------------------------------------
#define QS_B   0
#define KS_B   (QS_B + 128 * 136 * 2)
#define VT_B   (KS_B + 128 * 136 * 2)
#define PS_B   (VT_B + 128 * 72 * 2)
#define RED_B  (PS_B + 128 * 72 * 2)
#define FL_SMEM (RED_B + 4 * 128 * 4)

__global__ __launch_bounds__(256) void flash_h() {
    extern __shared__ char smc[];
    __half (*Qs)[136]  = (__half(*)[136])(smc + QS_B);
    __half (*Ks)[136]  = (__half(*)[136])(smc + KS_B);   // [buf*64 + row]
    __half (*Vts)[72]  = (__half(*)[72])(smc + VT_B);    // [d][k]
    __half (*Ps)[72]   = (__half(*)[72])(smc + PS_B);    // [q][k]
    float* red         = (float*)(smc + RED_B);          // [wq*128 + row]

    int qb = 15 - (int)blockIdx.x;       // long CTAs first
    int h  = blockIdx.y;
    int tid = threadIdx.x, lane = tid & 31, wid = tid >> 5;
    int wm = (wid >> 2) * 64;            // 0 / 64
    int wq = wid & 3;                    // n-warp index
    int g = lane >> 2, t = lane & 3;
    int kv = h >> 2;

#pragma unroll
    for (int j = 0; j < 8; j++) {
        int id = j * 256 + tid;
        int row = id >> 4, c8 = (id & 15) * 8;
        cp_async16(smem_u32(&Qs[row][c8]),
                   g_Qh + (size_t)(qb * 128 + row) * HID + h * HD + c8);
    }
    CP_COMMIT();
#pragma unroll
    for (int j = 0; j < 4; j++) {
        int id = j * 256 + tid;
        int row = id >> 4, c8 = (id & 15) * 8;
        cp_async16(smem_u32(&Ks[row][c8]),
                   g_Kh + (size_t)row * KVD + kv * HD + c8);
    }
    CP_COMMIT();
    asm volatile("cp.async.wait_group 0;" ::: "memory");
    __syncthreads();

    float Oacc[4][4][4] = {};
    float mrow[4][2], lsum[4][2];
#pragma unroll
    for (int i = 0; i < 4; i++) { mrow[i][0] = mrow[i][1] = -1e30f; lsum[i][0] = lsum[i][1] = 0.f; }

    int kbmax = 2 * qb + 1;
    for (int kb = 0; kb <= kbmax; kb++) {
        int cur = kb & 1;
        if (kb) {
            asm volatile("cp.async.wait_group 0;" ::: "memory");
            __syncthreads();
        }
#pragma unroll
        for (int j = 0; j < 4; j++) {
            int id = j * 256 + tid;
            int row = id >> 3, c8 = (id & 7) * 8;
            cp_async16(smem_u32(&Vts[row][c8]),
                       g_Vth + (size_t)(kv * HD + row) * SQ + kb * 64 + c8);
        }
        CP_COMMIT();
        int haveK = kb < kbmax;
        if (haveK) {
#pragma unroll
            for (int j = 0; j < 4; j++) {
                int id = j * 256 + tid;
                int row = id >> 4, c8 = (id & 15) * 8;
                cp_async16(smem_u32(&Ks[(cur ^ 1) * 64 + row][c8]),
                           g_Kh + (size_t)((kb + 1) * 64 + row) * KVD + kv * HD + c8);
            }
            CP_COMMIT();
        }

        float sacc[4][2][4] = {};
#pragma unroll
        for (int ks = 0; ks < 8; ks++) {
            uint32_t a[4][4], b[2][2];
#pragma unroll
            for (int i = 0; i < 4; i++) {
                a[i][0] = *(const uint32_t*)&Qs[wm + i * 16 + g][ks * 16 + 2 * t];
                a[i][1] = *(const uint32_t*)&Qs[wm + i * 16 + g + 8][ks * 16 + 2 * t];
                a[i][2] = *(const uint32_t*)&Qs[wm + i * 16 + g][ks * 16 + 2 * t + 8];
                a[i][3] = *(const uint32_t*)&Qs[wm + i * 16 + g + 8][ks * 16 + 2 * t + 8];
            }
#pragma unroll
            for (int j = 0; j < 2; j++) {
                b[j][0] = *(const uint32_t*)&Ks[cur * 64 + wq * 16 + j * 8 + g][ks * 16 + 2 * t];
                b[j][1] = *(const uint32_t*)&Ks[cur * 64 + wq * 16 + j * 8 + g][ks * 16 + 2 * t + 8];
            }
#pragma unroll
            for (int i = 0; i < 4; i++)
#pragma unroll
                for (int j = 0; j < 2; j++)
                    mma_h(sacc[i][j], a[i], b[j]);
        }

        if (kb >= 2 * qb) {
#pragma unroll
            for (int i = 0; i < 4; i++)
#pragma unroll
                for (int j = 0; j < 2; j++)
#pragma unroll
                    for (int e = 0; e < 4; e++) {
                        int grow = qb * 128 + wm + i * 16 + g + (e >> 1) * 8;
                        int gcol = kb * 64 + wq * 16 + j * 8 + 2 * t + (e & 1);
                        if (gcol > grow) sacc[i][j][e] = -1e30f;
                    }
        }

        float pm[4][2];
#pragma unroll
        for (int i = 0; i < 4; i++)
#pragma unroll
            for (int hf = 0; hf < 2; hf++) {
                float v = fmaxf(fmaxf(sacc[i][0][hf * 2], sacc[i][0][hf * 2 + 1]),
                                fmaxf(sacc[i][1][hf * 2], sacc[i][1][hf * 2 + 1]));
                v = fmaxf(v, __shfl_xor_sync(0xffffffffu, v, 1));
                v = fmaxf(v, __shfl_xor_sync(0xffffffffu, v, 2));
                pm[i][hf] = v;
            }
        if (t == 0) {
#pragma unroll
            for (int i = 0; i < 4; i++) {
                red[wq * 128 + wm + i * 16 + g]     = pm[i][0];
                red[wq * 128 + wm + i * 16 + g + 8] = pm[i][1];
            }
        }
        __syncthreads();
        float mnew[4][2], fac[4][2];
#pragma unroll
        for (int i = 0; i < 4; i++)
#pragma unroll
            for (int hf = 0; hf < 2; hf++) {
                int r = wm + i * 16 + g + hf * 8;
                float v = fmaxf(fmaxf(red[r], red[128 + r]),
                                fmaxf(red[256 + r], red[384 + r]));
                v = fmaxf(v, mrow[i][hf]);
                fac[i][hf] = __expf(mrow[i][hf] - v);
                mnew[i][hf] = v;
                mrow[i][hf] = v;
            }
        __syncthreads();

        float psum[4][2] = {};
#pragma unroll
        for (int i = 0; i < 4; i++)
#pragma unroll
            for (int hf = 0; hf < 2; hf++) {
                float m = mnew[i][hf];
                float p0 = __expf(sacc[i][0][hf * 2] - m);
                float p1 = __expf(sacc[i][0][hf * 2 + 1] - m);
                float p2 = __expf(sacc[i][1][hf * 2] - m);
                float p3 = __expf(sacc[i][1][hf * 2 + 1] - m);
                psum[i][hf] = (p0 + p1) + (p2 + p3);
                int r = wm + i * 16 + g + hf * 8;
                *(__half2*)&Ps[r][wq * 16 + 2 * t]     = __floats2half2_rn(p0, p1);
                *(__half2*)&Ps[r][wq * 16 + 8 + 2 * t] = __floats2half2_rn(p2, p3);
            }
#pragma unroll
        for (int i = 0; i < 4; i++)
#pragma unroll
            for (int hf = 0; hf < 2; hf++) {
                float v = psum[i][hf];
                v += __shfl_xor_sync(0xffffffffu, v, 1);
                v += __shfl_xor_sync(0xffffffffu, v, 2);
                psum[i][hf] = v;
            }
        if (t == 0) {
#pragma unroll
            for (int i = 0; i < 4; i++) {
                red[wq * 128 + wm + i * 16 + g]     = psum[i][0];
                red[wq * 128 + wm + i * 16 + g + 8] = psum[i][1];
            }
        }
        if (haveK) asm volatile("cp.async.wait_group 1;" ::: "memory");
        else       asm volatile("cp.async.wait_group 0;" ::: "memory");
        __syncthreads();

#pragma unroll
        for (int i = 0; i < 4; i++)
#pragma unroll
            for (int hf = 0; hf < 2; hf++) {
                int r = wm + i * 16 + g + hf * 8;
                float s = (red[r] + red[128 + r]) + (red[256 + r] + red[384 + r]);
                lsum[i][hf] = lsum[i][hf] * fac[i][hf] + s;
            }
#pragma unroll
        for (int i = 0; i < 4; i++)
#pragma unroll
            for (int j = 0; j < 4; j++) {
                Oacc[i][j][0] *= fac[i][0]; Oacc[i][j][1] *= fac[i][0];
                Oacc[i][j][2] *= fac[i][1]; Oacc[i][j][3] *= fac[i][1];
            }

        int wn = wq * 32;
#pragma unroll
        for (int ks = 0; ks < 4; ks++) {
            uint32_t a[4][4], b[4][2];
#pragma unroll
            for (int i = 0; i < 4; i++) {
                a[i][0] = *(const uint32_t*)&Ps[wm + i * 16 + g][ks * 16 + 2 * t];
                a[i][1] = *(const uint32_t*)&Ps[wm + i * 16 + g + 8][ks * 16 + 2 * t];
                a[i][2] = *(const uint32_t*)&Ps[wm + i * 16 + g][ks * 16 + 2 * t + 8];
                a[i][3] = *(const uint32_t*)&Ps[wm + i * 16 + g + 8][ks * 16 + 2 * t + 8];
            }
#pragma unroll
            for (int j = 0; j < 4; j++) {
                b[j][0] = *(const uint32_t*)&Vts[wn + j * 8 + g][ks * 16 + 2 * t];
                b[j][1] = *(const uint32_t*)&Vts[wn + j * 8 + g][ks * 16 + 2 * t + 8];
            }
#pragma unroll
            for (int i = 0; i < 4; i++)
#pragma unroll
                for (int j = 0; j < 4; j++)
                    mma_h(Oacc[i][j], a[i], b[j]);
        }
    }

    int wn = wq * 32;
#pragma unroll
    for (int i = 0; i < 4; i++) {
        float inv0 = 1.f / lsum[i][0];
        float inv1 = 1.f / lsum[i][1];
#pragma unroll
        for (int j = 0; j < 4; j++) {
            int r0 = qb * 128 + wm + i * 16 + g;
            int cc = h * HD + wn + j * 8 + 2 * t;
            *(__half2*)(g_Ah + (size_t)r0 * HID + cc) =
                __floats2half2_rn(Oacc[i][j][0] * inv0, Oacc[i][j][1] * inv0);
            *(__half2*)(g_Ah + (size_t)(r0 + 8) * HID + cc) =
                __floats2half2_rn(Oacc[i][j][2] * inv1, Oacc[i][j][3] * inv1);
        }
    }
}

// ---------------------------------------------------------------------------
// RoPE: reads fp32 fused QKV (row stride 6144), writes fp16 g_Qh / g_Kh.
// ---------------------------------------------------------------------------
__global__ void rope_kernel(const int* __restrict__ pos) {
    __shared__ float cs[64], sn[64];
    int s = blockIdx.x;
    float p = (float)pos[s];
    if (threadIdx.x < 64) {
        int d = threadIdx.x;
        float freq = (float)pow(10000.0, -(double)d / 64.0);
        float ang = p * freq;
        sincosf(ang, &sn[d], &cs[d]);
    }
    __syncthreads();
    const float scale = 0.08838834764831845f;  // 1/sqrt(128)
    for (int item = threadIdx.x; item < (NH + NKV) * 64; item += blockDim.x) {
        int head = item >> 6;
        int d    = item & 63;
        const float* base;
        __half* dst;
        if (head < NH) {
            base = g_QKV + (size_t)s * QKVD + head * HD;
            dst  = g_Qh  + (size_t)s * HID + head * HD;
        } else {
            base = g_QKV + (size_t)s * QKVD + HID + (head - NH) * HD;
            dst  = g_Kh  + (size_t)s * KVD + (head - NH) * HD;
        }
        float x1 = base[d], x2 = base[d + 64];
        float c = cs[d], si = sn[d];
        float o1 = x1 * c - x2 * si;
        float o2 = x2 * c + x1 * si;
        if (head < NH) { o1 *= scale; o2 *= scale; }
        dst[d]      = __float2half_rn(o1);
        dst[d + 64] = __float2half_rn(o2);
    }
}

// ---------------------------------------------------------------------------
// V transpose + fp16: g_Vth[kv*HD + d][s] = fp16(QKV_V[s][kv*HD + d])
// ---------------------------------------------------------------------------
__global__ __launch_bounds__(256) void transpose_v_kernel() {
    __shared__ float tb[32][33];
    int s0 = blockIdx.x * 32, d0 = blockIdx.y * 32, kv = blockIdx.z;
    int tx = threadIdx.x, ty = threadIdx.y;   // (32, 8)
#pragma unroll
    for (int i = 0; i < 4; i++)
        tb[ty + i * 8][tx] =
            g_QKV[(size_t)(s0 + ty + i * 8) * QKVD + HID + KVD + kv * HD + d0 + tx];
    __syncthreads();
#pragma unroll
    for (int i = 0; i < 4; i++)
        g_Vth[(size_t)(kv * HD + d0 + ty + i * 8) * SQ + s0 + tx] =
            __float2half_rn(tb[tx][ty + i * 8]);
}

// ---------------------------------------------------------------------------
extern "C" void kernel_launch(void* const* d_in, const int* in_sizes, int n_in,
                              void* d_out, int out_size) {
    (void)in_sizes; (void)n_in; (void)out_size;
    const float* X   = (const float*)d_in[0];
    const int*   pos = (const int*)d_in[1];
    const float* Wq  = (const float*)d_in[2];
    const float* Wk  = (const float*)d_in[3];
    const float* Wv  = (const float*)d_in[4];
    const float* Wo  = (const float*)d_in[5];
    float* out = (float*)d_out;

    float* QKVd;
    __half *Xh, *Wqkvh, *Woh, *Ah;
    cudaGetSymbolAddress((void**)&QKVd,  g_QKV);
    cudaGetSymbolAddress((void**)&Xh,    g_Xh);
    cudaGetSymbolAddress((void**)&Wqkvh, g_Wqkvh);
    cudaGetSymbolAddress((void**)&Woh,   g_Woh);
    cudaGetSymbolAddress((void**)&Ah,    g_Ah);

    cudaFuncSetAttribute(flash_h, cudaFuncAttributeMaxDynamicSharedMemorySize, FL_SMEM);
    cudaFuncSetAttribute(gemm_h,  cudaFuncAttributeMaxDynamicSharedMemorySize, GH_SMEM);

    // Convert inputs fp32 -> fp16 (RN); W[q|k|v] concatenated row-wise
    {
        int n4;
        n4 = SQ * HID / 4;
        f2h_kernel<<<(n4 + 255) / 256, 256>>>((const float4*)X, (uint2*)Xh, n4);
        n4 = HID * HID / 4;
        f2h_kernel<<<(n4 + 255) / 256, 256>>>((const float4*)Wq, (uint2*)Wqkvh, n4);
        n4 = KVD * HID / 4;
        f2h_kernel<<<(n4 + 255) / 256, 256>>>((const float4*)Wk,
                                              (uint2*)(Wqkvh + (size_t)HID * HID), n4);
        f2h_kernel<<<(n4 + 255) / 256, 256>>>((const float4*)Wv,
                                              (uint2*)(Wqkvh + (size_t)(HID + KVD) * HID), n4);
        n4 = HID * HID / 4;
        f2h_kernel<<<(n4 + 255) / 256, 256>>>((const float4*)Wo, (uint2*)Woh, n4);
    }

    // Fused QKV projection: C[2048, 6144], then O projection at the end
    gemm_h<<<dim3(QKVD / 128, SQ / 128), 256, GH_SMEM>>>(Xh, Wqkvh, QKVd, SQ, QKVD, HID);
    rope_kernel<<<SQ, 256>>>(pos);
    transpose_v_kernel<<<dim3(SQ / 32, HD / 32, NKV), dim3(32, 8)>>>();
    flash_h<<<dim3(SQ / 128, NH), 256, FL_SMEM>>>();
    gemm_h<<<dim3(HID / 128, SQ / 128), 256, GH_SMEM>>>(Ah, Woh, out, SQ, HID, HID);
}

// round 16
// speedup vs baseline: 1.1562x; 1.1562x over previous
#include <cuda_runtime.h>
#include <cuda_fp16.h>
#include <math.h>
#include <float.h>
#include <stdint.h>

#define SQ   2048
#define HID  4096
#define NH   32
#define NKV  8
#define HD   128
#define KVD  1024   // NKV * HD
#define QKVD 6144   // HID + 2*KVD

// Scratch (allocation-free rule: __device__ globals)
__device__ float  g_QKV[SQ * QKVD];      // 48 MB  fused QKV proj out fp32
__device__ __half g_Qh[SQ * HID];        // 16 MB  post-RoPE, scaled, fp16
__device__ __half g_Kh[SQ * KVD];        // 4 MB   post-RoPE fp16
__device__ __half g_Vth[KVD * SQ];       // 4 MB   V^T [kv*HD+d][s] fp16
__device__ __half g_Ah[SQ * HID];        // 16 MB  attention out fp16
__device__ __half g_Xh[SQ * HID];        // 16 MB
__device__ __half g_Wqkvh[QKVD * HID];   // 48 MB  [Wq; Wk; Wv] rows
__device__ __half g_Woh[HID * HID];      // 32 MB

__device__ __forceinline__ uint32_t smem_u32(const void* p) {
    uint32_t a;
    asm("{ .reg .u64 t; cvta.to.shared.u64 t, %1; cvt.u32.u64 %0, t; }" : "=r"(a) : "l"(p));
    return a;
}
__device__ __forceinline__ void cp_async16(uint32_t dst, const void* src) {
    asm volatile("cp.async.cg.shared.global [%0], [%1], 16;" :: "r"(dst), "l"(src) : "memory");
}
#define CP_COMMIT() asm volatile("cp.async.commit_group;" ::: "memory")

__device__ __forceinline__ void mma_h(float* c, const uint32_t* a, const uint32_t* b) {
    asm volatile(
        "mma.sync.aligned.m16n8k16.row.col.f32.f16.f16.f32 "
        "{%0,%1,%2,%3}, {%4,%5,%6,%7}, {%8,%9}, {%0,%1,%2,%3};"
        : "+f"(c[0]), "+f"(c[1]), "+f"(c[2]), "+f"(c[3])
        : "r"(a[0]), "r"(a[1]), "r"(a[2]), "r"(a[3]), "r"(b[0]), "r"(b[1]));
}
__device__ __forceinline__ void ldsm4(uint32_t& r0, uint32_t& r1, uint32_t& r2,
                                      uint32_t& r3, uint32_t addr) {
    asm volatile("ldmatrix.sync.aligned.m8n8.x4.shared.b16 {%0,%1,%2,%3}, [%4];"
                 : "=r"(r0), "=r"(r1), "=r"(r2), "=r"(r3) : "r"(addr));
}

// ---------------------------------------------------------------------------
// fp32 -> fp16 (RN) conversion
// ---------------------------------------------------------------------------
__global__ void f2h_kernel(const float4* __restrict__ in,
                           uint2* __restrict__ out, int n4) {
    int i = blockIdx.x * blockDim.x + threadIdx.x;
    if (i < n4) {
        float4 v = in[i];
        __half2 lo = __floats2half2_rn(v.x, v.y);
        __half2 hi = __floats2half2_rn(v.z, v.w);
        out[i] = make_uint2(*(uint32_t*)&lo, *(uint32_t*)&hi);
    }
}

// ---------------------------------------------------------------------------
// fp16 GEMM (R13, proven local optimum): C[M,N] = A[M,K] @ B[N,K]^T.
// CTA 128x128, 8 warps (2x4), warp tile 64x32, K staged 32 halves,
// double-buffered cp.async, ldmatrix fragment loads, stride 40 halves.
// ---------------------------------------------------------------------------
__global__ __launch_bounds__(256) void gemm_h(const __half* __restrict__ A,
                                              const __half* __restrict__ B,
                                              float* __restrict__ C,
                                              int M, int N, int K) {
    __shared__ __half As[2][128][40];
    __shared__ __half Bs[2][128][40];
    int tid = threadIdx.x, lane = tid & 31, wid = tid >> 5;
    int wm = (wid >> 2) * 64;
    int wn = (wid & 3) * 32;
    int g = lane >> 2, t = lane & 3;
    int lrow = tid >> 1, lcol = (tid & 1) * 16;
    uint32_t sA[2], sB[2];
    sA[0] = smem_u32(&As[0][lrow][lcol]); sA[1] = smem_u32(&As[1][lrow][lcol]);
    sB[0] = smem_u32(&Bs[0][lrow][lcol]); sB[1] = smem_u32(&Bs[1][lrow][lcol]);
    int l16 = lane & 15, lk8 = (lane >> 4) * 8;
    uint32_t aB[2], bB[2];
    aB[0] = smem_u32(&As[0][wm + l16][lk8]); aB[1] = smem_u32(&As[1][wm + l16][lk8]);
    bB[0] = smem_u32(&Bs[0][wn + l16][lk8]); bB[1] = smem_u32(&Bs[1][wn + l16][lk8]);

    float acc[4][4][4] = {};

    int m0 = blockIdx.y * 128, n0 = blockIdx.x * 128;
    const __half* Ag = A + (size_t)(m0 + lrow) * K + lcol;
    const __half* Bg = B + (size_t)(n0 + lrow) * K + lcol;
    int S = K >> 5;   // stages of 32 halves

#define GH_LOAD(st) do { \
        int _b = (st) & 1; \
        const __half* _a  = Ag + (st) * 32; \
        const __half* _bg = Bg + (st) * 32; \
        cp_async16(sA[_b], _a);  cp_async16(sA[_b] + 16, _a + 8); \
        cp_async16(sB[_b], _bg); cp_async16(sB[_b] + 16, _bg + 8); \
        CP_COMMIT(); \
    } while (0)

    GH_LOAD(0);
    GH_LOAD(1);

    for (int kt = 0; kt < S; kt++) {
        if (kt < S - 1) asm volatile("cp.async.wait_group 1;" ::: "memory");
        else            asm volatile("cp.async.wait_group 0;" ::: "memory");
        __syncthreads();
        int buf = kt & 1;
#pragma unroll
        for (int kk = 0; kk < 2; kk++) {        // two k16 steps; byte off kk*32
            uint32_t a[4][4], b[4][2];
#pragma unroll
            for (int i = 0; i < 4; i++)
                ldsm4(a[i][0], a[i][1], a[i][2], a[i][3],
                      aB[buf] + (uint32_t)(i * 16 * 80 + kk * 32));
#pragma unroll
            for (int p = 0; p < 2; p++)
                ldsm4(b[2 * p][0], b[2 * p + 1][0], b[2 * p][1], b[2 * p + 1][1],
                      bB[buf] + (uint32_t)(p * 16 * 80 + kk * 32));
#pragma unroll
            for (int i = 0; i < 4; i++)
#pragma unroll
                for (int j = 0; j < 4; j++)
                    mma_h(acc[i][j], a[i], b[j]);
        }
        __syncthreads();
        if (kt + 2 < S) GH_LOAD(kt + 2);
    }
#undef GH_LOAD

#pragma unroll
    for (int i = 0; i < 4; i++) {
#pragma unroll
        for (int j = 0; j < 4; j++) {
            int r0 = m0 + wm + i * 16 + g;
            int cc = n0 + wn + j * 8 + t * 2;
            *(float2*)(C + (size_t)r0 * N + cc)       = make_float2(acc[i][j][0], acc[i][j][1]);
            *(float2*)(C + (size_t)(r0 + 8) * N + cc) = make_float2(acc[i][j][2], acc[i][j][3]);
        }
    }
}

// ---------------------------------------------------------------------------
// Fused flash attention, k-tile 128: per CTA one 128-row q-tile of one head.
// Halves the iteration count (and thus softmax/barrier overhead) vs k-tile 64.
// Smem (halves, stride 136): Qs[128] | Ks[2][128] | Vts[128] | Ps[128]
//                            + red[4*128] floats = 176128 B (1 CTA/SM).
// ---------------------------------------------------------------------------
#define QS_B   0
#define KS_B   (QS_B + 128 * 136 * 2)
#define VT_B   (KS_B + 2 * 128 * 136 * 2)
#define PS_B   (VT_B + 128 * 136 * 2)
#define RED_B  (PS_B + 128 * 136 * 2)
#define FL_SMEM (RED_B + 4 * 128 * 4)

__global__ __launch_bounds__(256) void flash_h() {
    extern __shared__ char smc[];
    __half (*Qs)[136]  = (__half(*)[136])(smc + QS_B);
    __half (*Ks)[136]  = (__half(*)[136])(smc + KS_B);   // [buf*128 + row]
    __half (*Vts)[136] = (__half(*)[136])(smc + VT_B);   // [d][k]
    __half (*Ps)[136]  = (__half(*)[136])(smc + PS_B);   // [q][k]
    float* red         = (float*)(smc + RED_B);          // [wq*128 + row]

    int qb = 15 - (int)blockIdx.x;       // long CTAs first
    int h  = blockIdx.y;
    int tid = threadIdx.x, lane = tid & 31, wid = tid >> 5;
    int wm = (wid >> 2) * 64;            // 0 / 64
    int wq = wid & 3;                    // n-warp index
    int g = lane >> 2, t = lane & 3;
    int kv = h >> 2;

    // ---- prologue: load Q tile (128x128 halves) and K tile 0 (128x128) ----
#pragma unroll
    for (int j = 0; j < 8; j++) {
        int id = j * 256 + tid;
        int row = id >> 4, c8 = (id & 15) * 8;
        cp_async16(smem_u32(&Qs[row][c8]),
                   g_Qh + (size_t)(qb * 128 + row) * HID + h * HD + c8);
    }
    CP_COMMIT();
#pragma unroll
    for (int j = 0; j < 8; j++) {
        int id = j * 256 + tid;
        int row = id >> 4, c8 = (id & 15) * 8;
        cp_async16(smem_u32(&Ks[row][c8]),
                   g_Kh + (size_t)row * KVD + kv * HD + c8);
    }
    CP_COMMIT();
    asm volatile("cp.async.wait_group 0;" ::: "memory");
    __syncthreads();

    float Oacc[4][4][4] = {};
    float mrow[4][2], lsum[4][2];
#pragma unroll
    for (int i = 0; i < 4; i++) { mrow[i][0] = mrow[i][1] = -1e30f; lsum[i][0] = lsum[i][1] = 0.f; }

    for (int kb = 0; kb <= qb; kb++) {
        int cur = kb & 1;
        if (kb) {
            asm volatile("cp.async.wait_group 0;" ::: "memory");
            __syncthreads();
        }
        // issue V[kb] (own group), then K[kb+1] (own group)
#pragma unroll
        for (int j = 0; j < 8; j++) {
            int id = j * 256 + tid;
            int row = id >> 4, c8 = (id & 15) * 8;
            cp_async16(smem_u32(&Vts[row][c8]),
                       g_Vth + (size_t)(kv * HD + row) * SQ + kb * 128 + c8);
        }
        CP_COMMIT();
        int haveK = kb < qb;
        if (haveK) {
#pragma unroll
            for (int j = 0; j < 8; j++) {
                int id = j * 256 + tid;
                int row = id >> 4, c8 = (id & 15) * 8;
                cp_async16(smem_u32(&Ks[(cur ^ 1) * 128 + row][c8]),
                           g_Kh + (size_t)((kb + 1) * 128 + row) * KVD + kv * HD + c8);
            }
            CP_COMMIT();
        }

        // ---- S = Q @ K^T : 128x128, k=128 -> 8 k16 steps, warp n-tile 32 ----
        float sacc[4][4][4] = {};
#pragma unroll
        for (int ks = 0; ks < 8; ks++) {
            uint32_t a[4][4], b[4][2];
#pragma unroll
            for (int i = 0; i < 4; i++) {
                a[i][0] = *(const uint32_t*)&Qs[wm + i * 16 + g][ks * 16 + 2 * t];
                a[i][1] = *(const uint32_t*)&Qs[wm + i * 16 + g + 8][ks * 16 + 2 * t];
                a[i][2] = *(const uint32_t*)&Qs[wm + i * 16 + g][ks * 16 + 2 * t + 8];
                a[i][3] = *(const uint32_t*)&Qs[wm + i * 16 + g + 8][ks * 16 + 2 * t + 8];
            }
#pragma unroll
            for (int j = 0; j < 4; j++) {
                b[j][0] = *(const uint32_t*)&Ks[cur * 128 + wq * 32 + j * 8 + g][ks * 16 + 2 * t];
                b[j][1] = *(const uint32_t*)&Ks[cur * 128 + wq * 32 + j * 8 + g][ks * 16 + 2 * t + 8];
            }
#pragma unroll
            for (int i = 0; i < 4; i++)
#pragma unroll
                for (int j = 0; j < 4; j++)
                    mma_h(sacc[i][j], a[i], b[j]);
        }

        // ---- causal mask on the diagonal k-tile ----
        if (kb == qb) {
#pragma unroll
            for (int i = 0; i < 4; i++)
#pragma unroll
                for (int j = 0; j < 4; j++)
#pragma unroll
                    for (int e = 0; e < 4; e++) {
                        int grow = wm + i * 16 + g + (e >> 1) * 8;
                        int gcol = wq * 32 + j * 8 + 2 * t + (e & 1);
                        if (gcol > grow) sacc[i][j][e] = -1e30f;
                    }
        }

        // ---- online softmax ----
        float pm[4][2];
#pragma unroll
        for (int i = 0; i < 4; i++)
#pragma unroll
            for (int hf = 0; hf < 2; hf++) {
                float v = fmaxf(fmaxf(sacc[i][0][hf * 2], sacc[i][0][hf * 2 + 1]),
                                fmaxf(sacc[i][1][hf * 2], sacc[i][1][hf * 2 + 1]));
                float w = fmaxf(fmaxf(sacc[i][2][hf * 2], sacc[i][2][hf * 2 + 1]),
                                fmaxf(sacc[i][3][hf * 2], sacc[i][3][hf * 2 + 1]));
                v = fmaxf(v, w);
                v = fmaxf(v, __shfl_xor_sync(0xffffffffu, v, 1));
                v = fmaxf(v, __shfl_xor_sync(0xffffffffu, v, 2));
                pm[i][hf] = v;
            }
        if (t == 0) {
#pragma unroll
            for (int i = 0; i < 4; i++) {
                red[wq * 128 + wm + i * 16 + g]     = pm[i][0];
                red[wq * 128 + wm + i * 16 + g + 8] = pm[i][1];
            }
        }
        __syncthreads();
        float mnew[4][2], fac[4][2];
#pragma unroll
        for (int i = 0; i < 4; i++)
#pragma unroll
            for (int hf = 0; hf < 2; hf++) {
                int r = wm + i * 16 + g + hf * 8;
                float v = fmaxf(fmaxf(red[r], red[128 + r]),
                                fmaxf(red[256 + r], red[384 + r]));
                v = fmaxf(v, mrow[i][hf]);
                fac[i][hf] = __expf(mrow[i][hf] - v);
                mnew[i][hf] = v;
                mrow[i][hf] = v;
            }
        __syncthreads();   // before red reuse for sums

        float psum[4][2] = {};
#pragma unroll
        for (int i = 0; i < 4; i++)
#pragma unroll
            for (int hf = 0; hf < 2; hf++) {
                float m = mnew[i][hf];
                int r = wm + i * 16 + g + hf * 8;
                float s = 0.f;
#pragma unroll
                for (int j = 0; j < 4; j++) {
                    float p0 = __expf(sacc[i][j][hf * 2] - m);
                    float p1 = __expf(sacc[i][j][hf * 2 + 1] - m);
                    s += p0 + p1;
                    *(__half2*)&Ps[r][wq * 32 + j * 8 + 2 * t] = __floats2half2_rn(p0, p1);
                }
                psum[i][hf] = s;
            }
#pragma unroll
        for (int i = 0; i < 4; i++)
#pragma unroll
            for (int hf = 0; hf < 2; hf++) {
                float v = psum[i][hf];
                v += __shfl_xor_sync(0xffffffffu, v, 1);
                v += __shfl_xor_sync(0xffffffffu, v, 2);
                psum[i][hf] = v;
            }
        if (t == 0) {
#pragma unroll
            for (int i = 0; i < 4; i++) {
                red[wq * 128 + wm + i * 16 + g]     = psum[i][0];
                red[wq * 128 + wm + i * 16 + g + 8] = psum[i][1];
            }
        }
        // wait V (K may still be in flight); barrier covers Ps + red + Vts
        if (haveK) asm volatile("cp.async.wait_group 1;" ::: "memory");
        else       asm volatile("cp.async.wait_group 0;" ::: "memory");
        __syncthreads();

#pragma unroll
        for (int i = 0; i < 4; i++)
#pragma unroll
            for (int hf = 0; hf < 2; hf++) {
                int r = wm + i * 16 + g + hf * 8;
                float s = (red[r] + red[128 + r]) + (red[256 + r] + red[384 + r]);
                lsum[i][hf] = lsum[i][hf] * fac[i][hf] + s;
            }
        // rescale O
#pragma unroll
        for (int i = 0; i < 4; i++)
#pragma unroll
            for (int j = 0; j < 4; j++) {
                Oacc[i][j][0] *= fac[i][0]; Oacc[i][j][1] *= fac[i][0];
                Oacc[i][j][2] *= fac[i][1]; Oacc[i][j][3] *= fac[i][1];
            }

        // ---- O += P @ V : 128x128, k=128 -> 8 k16 steps, warp n-tile 32 ----
        int wn = wq * 32;
#pragma unroll
        for (int ks = 0; ks < 8; ks++) {
            uint32_t a[4][4], b[4][2];
#pragma unroll
            for (int i = 0; i < 4; i++) {
                a[i][0] = *(const uint32_t*)&Ps[wm + i * 16 + g][ks * 16 + 2 * t];
                a[i][1] = *(const uint32_t*)&Ps[wm + i * 16 + g + 8][ks * 16 + 2 * t];
                a[i][2] = *(const uint32_t*)&Ps[wm + i * 16 + g][ks * 16 + 2 * t + 8];
                a[i][3] = *(const uint32_t*)&Ps[wm + i * 16 + g + 8][ks * 16 + 2 * t + 8];
            }
#pragma unroll
            for (int j = 0; j < 4; j++) {
                b[j][0] = *(const uint32_t*)&Vts[wn + j * 8 + g][ks * 16 + 2 * t];
                b[j][1] = *(const uint32_t*)&Vts[wn + j * 8 + g][ks * 16 + 2 * t + 8];
            }
#pragma unroll
            for (int i = 0; i < 4; i++)
#pragma unroll
                for (int j = 0; j < 4; j++)
                    mma_h(Oacc[i][j], a[i], b[j]);
        }
    }

    // ---- epilogue: O / l, convert fp16, store ----
    int wn = wq * 32;
#pragma unroll
    for (int i = 0; i < 4; i++) {
        float inv0 = 1.f / lsum[i][0];
        float inv1 = 1.f / lsum[i][1];
#pragma unroll
        for (int j = 0; j < 4; j++) {
            int r0 = qb * 128 + wm + i * 16 + g;
            int cc = h * HD + wn + j * 8 + 2 * t;
            *(__half2*)(g_Ah + (size_t)r0 * HID + cc) =
                __floats2half2_rn(Oacc[i][j][0] * inv0, Oacc[i][j][1] * inv0);
            *(__half2*)(g_Ah + (size_t)(r0 + 8) * HID + cc) =
                __floats2half2_rn(Oacc[i][j][2] * inv1, Oacc[i][j][3] * inv1);
        }
    }
}

// ---------------------------------------------------------------------------
// RoPE: reads fp32 fused QKV (row stride 6144), writes fp16 g_Qh / g_Kh.
// ---------------------------------------------------------------------------
__global__ void rope_kernel(const int* __restrict__ pos) {
    __shared__ float cs[64], sn[64];
    int s = blockIdx.x;
    float p = (float)pos[s];
    if (threadIdx.x < 64) {
        int d = threadIdx.x;
        float freq = (float)pow(10000.0, -(double)d / 64.0);
        float ang = p * freq;
        sincosf(ang, &sn[d], &cs[d]);
    }
    __syncthreads();
    const float scale = 0.08838834764831845f;  // 1/sqrt(128)
    for (int item = threadIdx.x; item < (NH + NKV) * 64; item += blockDim.x) {
        int head = item >> 6;
        int d    = item & 63;
        const float* base;
        __half* dst;
        if (head < NH) {
            base = g_QKV + (size_t)s * QKVD + head * HD;
            dst  = g_Qh  + (size_t)s * HID + head * HD;
        } else {
            base = g_QKV + (size_t)s * QKVD + HID + (head - NH) * HD;
            dst  = g_Kh  + (size_t)s * KVD + (head - NH) * HD;
        }
        float x1 = base[d], x2 = base[d + 64];
        float c = cs[d], si = sn[d];
        float o1 = x1 * c - x2 * si;
        float o2 = x2 * c + x1 * si;
        if (head < NH) { o1 *= scale; o2 *= scale; }
        dst[d]      = __float2half_rn(o1);
        dst[d + 64] = __float2half_rn(o2);
    }
}

// ---------------------------------------------------------------------------
// V transpose + fp16: g_Vth[kv*HD + d][s] = fp16(QKV_V[s][kv*HD + d])
// ---------------------------------------------------------------------------
__global__ __launch_bounds__(256) void transpose_v_kernel() {
    __shared__ float tb[32][33];
    int s0 = blockIdx.x * 32, d0 = blockIdx.y * 32, kv = blockIdx.z;
    int tx = threadIdx.x, ty = threadIdx.y;   // (32, 8)
#pragma unroll
    for (int i = 0; i < 4; i++)
        tb[ty + i * 8][tx] =
            g_QKV[(size_t)(s0 + ty + i * 8) * QKVD + HID + KVD + kv * HD + d0 + tx];
    __syncthreads();
#pragma unroll
    for (int i = 0; i < 4; i++)
        g_Vth[(size_t)(kv * HD + d0 + ty + i * 8) * SQ + s0 + tx] =
            __float2half_rn(tb[tx][ty + i * 8]);
}

// ---------------------------------------------------------------------------
extern "C" void kernel_launch(void* const* d_in, const int* in_sizes, int n_in,
                              void* d_out, int out_size) {
    (void)in_sizes; (void)n_in; (void)out_size;
    const float* X   = (const float*)d_in[0];
    const int*   pos = (const int*)d_in[1];
    const float* Wq  = (const float*)d_in[2];
    const float* Wk  = (const float*)d_in[3];
    const float* Wv  = (const float*)d_in[4];
    const float* Wo  = (const float*)d_in[5];
    float* out = (float*)d_out;

    float* QKVd;
    __half *Xh, *Wqkvh, *Woh, *Ah;
    cudaGetSymbolAddress((void**)&QKVd,  g_QKV);
    cudaGetSymbolAddress((void**)&Xh,    g_Xh);
    cudaGetSymbolAddress((void**)&Wqkvh, g_Wqkvh);
    cudaGetSymbolAddress((void**)&Woh,   g_Woh);
    cudaGetSymbolAddress((void**)&Ah,    g_Ah);

    cudaFuncSetAttribute(flash_h, cudaFuncAttributeMaxDynamicSharedMemorySize, FL_SMEM);

    // Convert inputs fp32 -> fp16 (RN); W[q|k|v] concatenated row-wise
    {
        int n4;
        n4 = SQ * HID / 4;
        f2h_kernel<<<(n4 + 255) / 256, 256>>>((const float4*)X, (uint2*)Xh, n4);
        n4 = HID * HID / 4;
        f2h_kernel<<<(n4 + 255) / 256, 256>>>((const float4*)Wq, (uint2*)Wqkvh, n4);
        n4 = KVD * HID / 4;
        f2h_kernel<<<(n4 + 255) / 256, 256>>>((const float4*)Wk,
                                              (uint2*)(Wqkvh + (size_t)HID * HID), n4);
        f2h_kernel<<<(n4 + 255) / 256, 256>>>((const float4*)Wv,
                                              (uint2*)(Wqkvh + (size_t)(HID + KVD) * HID), n4);
        n4 = HID * HID / 4;
        f2h_kernel<<<(n4 + 255) / 256, 256>>>((const float4*)Wo, (uint2*)Woh, n4);
    }

    // Fused QKV projection: C[2048, 6144], then O projection at the end
    gemm_h<<<dim3(QKVD / 128, SQ / 128), 256>>>(Xh, Wqkvh, QKVd, SQ, QKVD, HID);
    rope_kernel<<<SQ, 256>>>(pos);
    transpose_v_kernel<<<dim3(SQ / 32, HD / 32, NKV), dim3(32, 8)>>>();
    flash_h<<<dim3(SQ / 128, NH), 256, FL_SMEM>>>();
    gemm_h<<<dim3(HID / 128, SQ / 128), 256>>>(Ah, Woh, out, SQ, HID, HID);
}